// round 11
// baseline (speedup 1.0000x reference)
#include <cuda_runtime.h>
#include <math.h>
#include <stdint.h>

#define BATCH 2
#define DIM 256
#define HEADS 8
#define NQ 4096
#define NU 1024
#define TOPK 4
#define NTK 16
#define ATT_SCALE 0.17677669529663687f

typedef unsigned long long u64;

__device__ __forceinline__ u64 dup2(float a) {
    u64 r; asm("mov.b64 %0, {%1, %1};" : "=l"(r) : "f"(a)); return r;
}
__device__ __forceinline__ void fma2(u64& d, u64 a, u64 b) {
    asm("fma.rn.f32x2 %0, %1, %2, %3;" : "=l"(d) : "l"(a), "l"(b), "l"(d));
}
__device__ __forceinline__ float2 unpk2(u64 v) {
    float2 r; asm("mov.b64 {%0, %1}, %2;" : "=f"(r.x), "=f"(r.y) : "l"(v)); return r;
}
__device__ __forceinline__ void cpasync16(uint32_t dst, const void* src) {
    asm volatile("cp.async.cg.shared.global [%0], [%1], 16;" :: "r"(dst), "l"(src));
}
#define CP_COMMIT() asm volatile("cp.async.commit_group;")
#define CP_WAIT0()  asm volatile("cp.async.wait_group 0;")
#define CP_WAIT1()  asm volatile("cp.async.wait_group 1;")

__device__ float g_qT [BATCH*HEADS*32*NQ];
__device__ float g_fkT[BATCH*HEADS*32*NQ];
__device__ float g_fvT[BATCH*HEADS*32*NQ];
__device__ float g_kT [BATCH*HEADS*32*NU];
__device__ float g_v  [BATCH*HEADS*NU*32];
__device__ float g_vt [BATCH*DIM*NU];
__device__ float g_xout[BATCH*DIM*NQ];
__device__ int   g_txi[16*NTK];

__device__ __forceinline__ void threefry2x32_k42(uint32_t x0, uint32_t x1,
                                                 uint32_t& o0, uint32_t& o1) {
    const uint32_t ks1 = 42u, ks2 = 42u ^ 0x1BD11BDAu;
    x1 += ks1;
#define TF_R(r) { x0 += x1; x1 = (x1 << (r)) | (x1 >> (32 - (r))); x1 ^= x0; }
    TF_R(13) TF_R(15) TF_R(26) TF_R(6)
    x0 += ks1; x1 += ks2 + 1u;
    TF_R(17) TF_R(29) TF_R(16) TF_R(24)
    x0 += ks2; x1 += 2u;
    TF_R(13) TF_R(15) TF_R(26) TF_R(6)
    x0 += 0u; x1 += ks1 + 3u;
    TF_R(17) TF_R(29) TF_R(16) TF_R(24)
    x0 += ks1; x1 += ks2 + 4u;
    TF_R(13) TF_R(15) TF_R(26) TF_R(6)
    x0 += ks2; x1 += 5u;
#undef TF_R
    o0 = x0; o1 = x1;
}

__device__ __forceinline__ float gumbel_at(uint32_t l) {
    uint32_t o0, o1;
    threefry2x32_k42(0u, l, o0, o1);
    uint32_t bits = o0 ^ o1;
    float u01 = __uint_as_float((bits >> 9) | 0x3F800000u) - 1.0f;
    const float TINY = 1.17549435e-38f;
    float u = fmaxf(TINY, u01 * (1.0f - TINY) + TINY);
    return -logf(-logf(u));
}

// ---------------- GEMM 128x128, 8x8 microtile, f32x2 ------------------------
__global__ void __launch_bounds__(256, 2)
gemm_kernel(const float* __restrict__ X,
            const float* __restrict__ W1, const float* __restrict__ B1,
            const float* __restrict__ W2, const float* __restrict__ B2,
            float* __restrict__ dst, int P, int mode)
{
    __shared__ float Xs[2][8][128];
    __shared__ float Wt[2][8][132];
    const int b = blockIdx.z, p0 = blockIdx.x * 128, o0 = blockIdx.y * 128;
    const int t = threadIdx.x, to = t >> 4, tp = t & 15;
    const int xc = t >> 5, xp4 = t & 31, woo = t >> 1, whalf = t & 1;

    const float* Xb = (mode == 2) ? (g_xout + (long)b * DIM * P) : (X + (long)b * DIM * P);
    int ow = o0 + woo;
    const float* wptr = (mode == 0 && ow >= 256) ? W2 + (ow - 256) * DIM : W1 + ow * DIM;

    float4 xr = *(const float4*)&Xb[(long)xc * P + p0 + xp4 * 4];
    float4 wr = *(const float4*)&wptr[whalf * 4];

    u64 acc2[8][4];
#pragma unroll
    for (int i = 0; i < 8; i++)
#pragma unroll
        for (int j = 0; j < 4; j++) acc2[i][j] = 0ULL;

    int buf = 0;
    for (int c0 = 0; c0 < DIM; c0 += 8) {
        *(float4*)&Xs[buf][xc][xp4 * 4] = xr;
        Wt[buf][whalf * 4 + 0][woo] = wr.x;
        Wt[buf][whalf * 4 + 1][woo] = wr.y;
        Wt[buf][whalf * 4 + 2][woo] = wr.z;
        Wt[buf][whalf * 4 + 3][woo] = wr.w;
        __syncthreads();
        if (c0 + 8 < DIM) {
            xr = *(const float4*)&Xb[(long)(c0 + 8 + xc) * P + p0 + xp4 * 4];
            wr = *(const float4*)&wptr[c0 + 8 + whalf * 4];
        }
#pragma unroll
        for (int k = 0; k < 8; k++) {
            float4 a0 = *(const float4*)&Wt[buf][k][to * 8];
            float4 a1 = *(const float4*)&Wt[buf][k][to * 8 + 4];
            ulonglong2 xl = *(const ulonglong2*)&Xs[buf][k][tp * 8];
            ulonglong2 xh = *(const ulonglong2*)&Xs[buf][k][tp * 8 + 4];
            u64 xp[4] = {xl.x, xl.y, xh.x, xh.y};
            float av[8] = {a0.x, a0.y, a0.z, a0.w, a1.x, a1.y, a1.z, a1.w};
#pragma unroll
            for (int i = 0; i < 8; i++) {
                u64 ad = dup2(av[i]);
#pragma unroll
                for (int j = 0; j < 4; j++) fma2(acc2[i][j], ad, xp[j]);
            }
        }
        buf ^= 1;
    }

    const int p = p0 + tp * 8;
#pragma unroll
    for (int i = 0; i < 8; i++) {
        int o = o0 + to * 8 + i;
        float bias = (mode == 0 && o >= 256) ? B2[o - 256] : B1[o];
        float r[8];
#pragma unroll
        for (int j = 0; j < 4; j++) {
            float2 f = unpk2(acc2[i][j]);
            r[j * 2] = f.x + bias; r[j * 2 + 1] = f.y + bias;
        }
        if (mode == 0) {
            if (o < 256) {
#pragma unroll
                for (int j = 0; j < 8; j++) r[j] *= ATT_SCALE;
                float* ptr = g_qT + ((long)(b * 8 + (o >> 5)) * 32 + (o & 31)) * NQ + p;
                *(float4*)&ptr[0] = make_float4(r[0], r[1], r[2], r[3]);
                *(float4*)&ptr[4] = make_float4(r[4], r[5], r[6], r[7]);
            } else {
                int e2 = o - 256, h = e2 >> 6, e = e2 & 63;
                float* base = (e < 32) ? g_fkT : g_fvT;
                float* ptr = base + ((long)(b * 8 + h) * 32 + (e & 31)) * NQ + p;
                *(float4*)&ptr[0] = make_float4(r[0], r[1], r[2], r[3]);
                *(float4*)&ptr[4] = make_float4(r[4], r[5], r[6], r[7]);
            }
        } else if (mode == 1) {
            int h = o >> 6, e = o & 63;
            if (e < 32) {
                float* ptr = g_kT + ((long)(b * 8 + h) * 32 + e) * NU + p;
                *(float4*)&ptr[0] = make_float4(r[0], r[1], r[2], r[3]);
                *(float4*)&ptr[4] = make_float4(r[4], r[5], r[6], r[7]);
            } else {
                int d = e - 32;
#pragma unroll
                for (int j = 0; j < 8; j++)
                    g_v[((long)(b * 8 + h) * NU + p + j) * 32 + d] = r[j];
                float* ptr = g_vt + ((long)(b * 256 + h * 32 + d)) * NU + p;
                *(float4*)&ptr[0] = make_float4(r[0], r[1], r[2], r[3]);
                *(float4*)&ptr[4] = make_float4(r[4], r[5], r[6], r[7]);
            }
        } else {
            float* ptr = dst + ((long)(b * 256 + o)) * NQ + p;
            *(float4*)&ptr[0] = make_float4(r[0], r[1], r[2], r[3]);
            *(float4*)&ptr[4] = make_float4(r[4], r[5], r[6], r[7]);
        }
    }
}

// ---------------- topk --------------------------------------------------------
__global__ void __launch_bounds__(256) topk_kernel() {
    const int bh = blockIdx.x, t = threadIdx.x, w = t >> 5, l = t & 31;
    __shared__ float qm[32], cv[32];
    __shared__ int ci[32], sel[TOPK];
    const float* qb = g_qT + (long)bh * 32 * NQ;
#pragma unroll
    for (int dd = 0; dd < 4; dd++) {
        int d = w * 4 + dd;
        float s = 0.0f;
        const float* row = qb + (long)d * NQ;
        for (int i = l; i < NQ; i += 32) s += row[i];
#pragma unroll
        for (int off = 16; off >= 1; off >>= 1) s += __shfl_xor_sync(~0u, s, off);
        if (l == 0) qm[d] = s * (1.0f / NQ);
    }
    __syncthreads();
    const float* kb = g_kT + (long)bh * 32 * NU;
    float v[4]; int id[4];
#pragma unroll
    for (int r = 0; r < 4; r++) {
        int m = t + r * 256;
        float s = 0.0f;
#pragma unroll
        for (int d = 0; d < 32; d++) s += qm[d] * kb[d * NU + m];
        v[r] = s + gumbel_at((uint32_t)(bh * NU + m));
        id[r] = m;
    }
#pragma unroll
    for (int it = 0; it < TOPK; it++) {
        float lv = v[0]; int li = id[0];
#pragma unroll
        for (int r = 1; r < 4; r++) if (v[r] > lv) { lv = v[r]; li = id[r]; }
#pragma unroll
        for (int off = 16; off >= 1; off >>= 1) {
            float ov = __shfl_xor_sync(~0u, lv, off);
            int oi = __shfl_xor_sync(~0u, li, off);
            if (ov > lv) { lv = ov; li = oi; }
        }
#pragma unroll
        for (int r = 0; r < 4; r++) if (id[r] == li) v[r] = -INFINITY;
        if (l == 0) { cv[w * 4 + it] = lv; ci[w * 4 + it] = li; }
    }
    __syncthreads();
    if (t < 32) {
        float lv = cv[t]; int li = ci[t];
#pragma unroll
        for (int it = 0; it < TOPK; it++) {
            float bv = lv; int bi = li;
#pragma unroll
            for (int off = 16; off >= 1; off >>= 1) {
                float ov = __shfl_xor_sync(~0u, bv, off);
                int oi = __shfl_xor_sync(~0u, bi, off);
                if (ov > bv) { bv = ov; bi = oi; }
            }
            if (li == bi) lv = -INFINITY;
            if (t == 0) sel[it] = bi;
        }
    }
    __syncthreads();
    if (t < NTK) {
        int grp = t / TOPK, kk = t % TOPK;
        int m = sel[kk];
        g_txi[bh * NTK + t] = ((m >> 5) * 2 + (grp >> 1)) * 64 + (m & 31) * 2 + (grp & 1);
    }
}

// ---------------- attention: race-free cp.async pipeline, 3 blocks/SM -------
#define OFF_QT  0        // [32][68]
#define OFF_KT  2176     // [32][128]
#define OFF_VS  6272     // [128][32]
#define OFF_PX  10368    // P[128][64] / OA[4][64][32]
#define OFF_LR  18560
#define OFF_TXI 18624    // int[16]
#define ATTN_SMEM_FLOATS 18640
#define OFF_OUT 2176            // [64][68]
#define OFF_TK  6528            // [16][32]
#define OFF_TV  7040            // [16][32]
#define OFF_SC  7552            // [64][17]
#define OFF_GS  10368           // [32][64]
#define OFF_GB  12416           // [32]

__global__ void __launch_bounds__(128, 3)
attn_kernel(const float* __restrict__ gate_w, const float* __restrict__ gate_b)
{
    extern __shared__ float sm[];
    const int bh = blockIdx.y, n0 = blockIdx.x * 64, t = threadIdx.x;
    const int b = bh >> 3, h = bh & 7;
    const int qg = t >> 4, mg = t & 15;
    const int ms = t >> 5, qg2 = (t >> 2) & 7, dg = t & 3;
    const uint32_t smb = (uint32_t)__cvta_generic_to_shared(sm);

    const float* kb = g_kT + (long)bh * 32 * NU;
    const float* vb = g_v  + (long)bh * NU * 32;

    const float* qb = g_qT + (long)bh * 32 * NQ + n0;
#pragma unroll
    for (int r = 0; r < 4; r++) {
        int f4 = t + r * 128;
        int d = f4 >> 4, qf = (f4 & 15) << 2;
        *(float4*)&sm[OFF_QT + d * 68 + qf] = *(const float4*)&qb[(long)d * NQ + qf];
    }
    if (t < NTK) ((int*)sm)[OFF_TXI + t] = g_txi[bh * NTK + t];

    // prologue: stage chunk 0 K and V (one group)
#pragma unroll
    for (int r = 0; r < 8; r++) {
        int idx = t + r * 128;
        int d = idx >> 5, c2 = idx & 31;
        int sl = ((c2 >> 1) + ((c2 & 1) << 4) + d) & 31;
        cpasync16(smb + (uint32_t)(OFF_KT + d * 128 + sl * 4) * 4u,
                  &kb[(long)d * NU + c2 * 4]);
    }
#pragma unroll
    for (int r = 0; r < 8; r++) {
        int idx = t + r * 128;
        cpasync16(smb + (uint32_t)(OFF_VS + idx * 4) * 4u, &vb[idx * 4]);
    }
    CP_COMMIT();
    CP_WAIT0();
    __syncthreads();

    u64 acc2[8][4];
    float runl[8];
#pragma unroll
    for (int i = 0; i < 8; i++) {
        runl[i] = 0.0f;
#pragma unroll
        for (int j = 0; j < 4; j++) acc2[i][j] = 0ULL;
    }

    const int sl0 = ((qg + mg) & 15) * 4, sl1 = ((qg + 8 + mg) & 15) * 4;

    for (int it = 0; it < 8; it++) {
        const int m0n = (it + 1) * 128;

        // ---- QK 8x8 on current KT ----
        u64 s2[8][4];
#pragma unroll
        for (int i = 0; i < 8; i++)
#pragma unroll
            for (int j = 0; j < 4; j++) s2[i][j] = 0ULL;
#pragma unroll 4
        for (int k = 0; k < 32; k++) {
            float4 qa = *(const float4*)&sm[OFF_QT + k * 68 + qg * 8];
            float4 qc = *(const float4*)&sm[OFF_QT + k * 68 + qg * 8 + 4];
            ulonglong2 k0 = *(const ulonglong2*)&sm[OFF_KT + k * 128 + ((mg + k) & 31) * 4];
            ulonglong2 k1 = *(const ulonglong2*)&sm[OFF_KT + k * 128 + ((mg + 16 + k) & 31) * 4];
            u64 kp[4] = {k0.x, k0.y, k1.x, k1.y};
            float qv[8] = {qa.x, qa.y, qa.z, qa.w, qc.x, qc.y, qc.z, qc.w};
#pragma unroll
            for (int i = 0; i < 8; i++) {
                u64 qd = dup2(qv[i]);
#pragma unroll
                for (int j = 0; j < 4; j++) fma2(s2[i][j], qd, kp[j]);
            }
        }
        // exp fused into transposed P store
#pragma unroll
        for (int jj = 0; jj < 4; jj++) {
            float ex[8], ey[8];
#pragma unroll
            for (int i = 0; i < 8; i++) {
                float2 f = unpk2(s2[i][jj]);
                ex[i] = __expf(f.x); ey[i] = __expf(f.y);
                runl[i] += ex[i] + ey[i];
            }
            int m0r = mg * 8 + jj * 2;
            *(float4*)&sm[OFF_PX + m0r * 64 + sl0] = make_float4(ex[0], ex[1], ex[2], ex[3]);
            *(float4*)&sm[OFF_PX + m0r * 64 + sl1] = make_float4(ex[4], ex[5], ex[6], ex[7]);
            *(float4*)&sm[OFF_PX + (m0r + 1) * 64 + sl0] = make_float4(ey[0], ey[1], ey[2], ey[3]);
            *(float4*)&sm[OFF_PX + (m0r + 1) * 64 + sl1] = make_float4(ey[4], ey[5], ey[6], ey[7]);
        }

        // VS(it) is the only pending group; it had all of QK to land.
        CP_WAIT0();
        __syncthreads();   // (1) KT reads done + VS(it)/P visible

        // stage next KT (safe: no one reads KT anymore; lands during AV)
        if (it < 7) {
#pragma unroll
            for (int r = 0; r < 8; r++) {
                int idx = t + r * 128;
                int d = idx >> 5, c2 = idx & 31;
                int sl = ((c2 >> 1) + ((c2 & 1) << 4) + d) & 31;
                cpasync16(smb + (uint32_t)(OFF_KT + d * 128 + sl * 4) * 4u,
                          &kb[(long)d * NU + m0n + c2 * 4]);
            }
            CP_COMMIT();
        }

        // ---- AV 8x8 ----
#pragma unroll 4
        for (int st = 0; st < 32; st++) {
            int m = ms * 32 + st, mgp = m >> 3;
            float4 p0 = *(const float4*)&sm[OFF_PX + m * 64 + ((qg2 + mgp) & 15) * 4];
            float4 p1 = *(const float4*)&sm[OFF_PX + m * 64 + ((qg2 + 8 + mgp) & 15) * 4];
            ulonglong2 v0 = *(const ulonglong2*)&sm[OFF_VS + m * 32 + dg * 8];
            ulonglong2 v1 = *(const ulonglong2*)&sm[OFF_VS + m * 32 + dg * 8 + 4];
            u64 vp[4] = {v0.x, v0.y, v1.x, v1.y};
            float pv[8] = {p0.x, p0.y, p0.z, p0.w, p1.x, p1.y, p1.z, p1.w};
#pragma unroll
            for (int i = 0; i < 8; i++) {
                u64 pd = dup2(pv[i]);
#pragma unroll
                for (int j = 0; j < 4; j++) fma2(acc2[i][j], pd, vp[j]);
            }
        }
        __syncthreads();   // (2) AV done: VS and PX free

        if (it < 7) {
            // stage next VS; then retire KT(it+1) (had all of AV to land)
#pragma unroll
            for (int r = 0; r < 8; r++) {
                int idx = t + r * 128;
                cpasync16(smb + (uint32_t)(OFF_VS + idx * 4) * 4u,
                          &vb[(long)m0n * 32 + idx * 4]);
            }
            CP_COMMIT();
            CP_WAIT1();
            __syncthreads();  // (3) KT(it+1) visible
        }
    }

#pragma unroll
    for (int i = 0; i < 8; i++) {
        float r = runl[i];
        r += __shfl_xor_sync(~0u, r, 8, 16);
        r += __shfl_xor_sync(~0u, r, 4, 16);
        r += __shfl_xor_sync(~0u, r, 2, 16);
        r += __shfl_xor_sync(~0u, r, 1, 16);
        if (mg == 0) sm[OFF_LR + qg * 8 + i] = r;
    }
    __syncthreads();

    // park AV partials OA[ms][q][32]
#pragma unroll
    for (int i = 0; i < 8; i++) {
        int q = qg2 * 8 + i;
        int base = OFF_PX + (ms * 64 + q) * 32 + dg * 8;
        float2 f0 = unpk2(acc2[i][0]), f1 = unpk2(acc2[i][1]);
        float2 f2 = unpk2(acc2[i][2]), f3 = unpk2(acc2[i][3]);
        *(float4*)&sm[base]     = make_float4(f0.x, f0.y, f1.x, f1.y);
        *(float4*)&sm[base + 4] = make_float4(f2.x, f2.y, f3.x, f3.y);
    }
    __syncthreads();

    // reduce -> coarse Out[q][d]; gather fine K/V
#pragma unroll
    for (int r = 0; r < 16; r++) {
        int idx = t + r * 128;
        int q = idx >> 5, d = idx & 31;
        float c = sm[OFF_PX + q * 32 + d] + sm[OFF_PX + 2048 + q * 32 + d]
                + sm[OFF_PX + 4096 + q * 32 + d] + sm[OFF_PX + 6144 + q * 32 + d];
        sm[OFF_OUT + q * 68 + d] = c / sm[OFF_LR + q];
    }
#pragma unroll
    for (int r = 0; r < 4; r++) {
        int idx = t + r * 128;
        int kk = idx >> 5, d = idx & 31;
        int m = ((int*)sm)[OFF_TXI + kk];
        sm[OFF_TK + kk * 32 + d] = g_fkT[((long)bh * 32 + d) * NQ + m];
        sm[OFF_TV + kk * 32 + d] = g_fvT[((long)bh * 32 + d) * NQ + m];
    }
    __syncthreads();

    // fine scores (q = t>>1, 8 keys each); load gate weights
    {
        const int q = t >> 1, kg = t & 1;
        float qv[32];
#pragma unroll
        for (int d = 0; d < 32; d++) qv[d] = sm[OFF_QT + d * 68 + q];
#pragma unroll
        for (int j = 0; j < 8; j++) {
            int kk = kg * 8 + j;
            float s = 0.0f;
#pragma unroll
            for (int d = 0; d < 32; d++) s += qv[d] * sm[OFF_TK + kk * 32 + d];
            sm[OFF_SC + q * 17 + kk] = __expf(s);
        }
    }
#pragma unroll
    for (int r = 0; r < 16; r++) sm[OFF_GS + t + r * 128] = gate_w[t + r * 128];
    if (t < 32) sm[OFF_GB + t] = gate_b[t];
    __syncthreads();
    if (t < 64) {
        float sum = 0.0f;
#pragma unroll
        for (int kk = 0; kk < NTK; kk++) sum += sm[OFF_SC + t * 17 + kk];
        sm[OFF_SC + t * 17 + 16] = 1.0f / sum;
    }
    __syncthreads();
    // refined (q = t>>1, 16 d each)
    {
        const int q = t >> 1, hf = t & 1;
        float inv = sm[OFF_SC + q * 17 + 16];
        float sc[NTK];
#pragma unroll
        for (int kk = 0; kk < NTK; kk++) sc[kk] = sm[OFF_SC + q * 17 + kk];
#pragma unroll
        for (int dd = 0; dd < 16; dd++) {
            int d = hf * 16 + dd;
            float r = 0.0f;
#pragma unroll
            for (int kk = 0; kk < NTK; kk++) r += sc[kk] * sm[OFF_TV + kk * 32 + d];
            sm[OFF_OUT + q * 68 + 32 + d] = r * inv;
        }
    }
    __syncthreads();
    // gate + combine (q = t>>1, 16 d each)
    {
        const int q = t >> 1, hf = t & 1;
        float ov[64];
#pragma unroll
        for (int c4 = 0; c4 < 16; c4++)
            *(float4*)&ov[c4 * 4] = *(const float4*)&sm[OFF_OUT + q * 68 + c4 * 4];
        float res[16];
#pragma unroll
        for (int dd = 0; dd < 16; dd++) {
            int d = hf * 16 + dd;
            float g = sm[OFF_GB + d];
#pragma unroll
            for (int c = 0; c < 64; c++) g += ov[c] * sm[OFF_GS + d * 64 + c];
            float gv = 1.0f / (1.0f + __expf(-g));
            res[dd] = gv * sm[OFF_OUT + q * 68 + 32 + d] + (1.0f - gv) * ov[d];
        }
        __syncthreads();
#pragma unroll
        for (int dd = 0; dd < 16; dd++)
            sm[OFF_OUT + q * 68 + hf * 16 + dd] = res[dd];
    }
    __syncthreads();

    float* xo = g_xout + ((long)(b * 256 + h * 32)) * NQ + n0;
#pragma unroll
    for (int r = 0; r < 16; r++) {
        int idx = t + r * 128;
        int d = idx >> 6, q = idx & 63;
        xo[(long)d * NQ + q] = sm[OFF_OUT + q * 68 + d];
    }
}

// ---------------- depthwise 7x7 + bilinear up + add -------------------------
__global__ void __launch_bounds__(256)
dwupadd_kernel(const float* __restrict__ pe_w, const float* __restrict__ pe_b)
{
    int bc = blockIdx.x, t = threadIdx.x;
    __shared__ float tile[38 * 38], wv[49], vpe[1024];
    const float* src = g_vt + (long)bc * NU;
    for (int idx = t; idx < 38 * 38; idx += 256) {
        int ii = idx / 38 - 3, jj = idx % 38 - 3;
        tile[idx] = (ii >= 0 && ii < 32 && jj >= 0 && jj < 32) ? src[ii * 32 + jj] : 0.0f;
    }
    int c = bc & 255;
    if (t < 49) wv[t] = pe_w[c * 49 + t];
    __syncthreads();
    float bias = pe_b[c];
    for (int idx = t; idx < NU; idx += 256) {
        int i = idx >> 5, j = idx & 31;
        float s = bias;
#pragma unroll
        for (int di = 0; di < 7; di++)
#pragma unroll
            for (int dj = 0; dj < 7; dj++)
                s += tile[(i + di) * 38 + (j + dj)] * wv[di * 7 + dj];
        vpe[idx] = s;
    }
    __syncthreads();
    float* xo = g_xout + (long)bc * NQ;
    for (int idx = t; idx < NQ; idx += 256) {
        int I = idx >> 6, J = idx & 63;
        int i0, i1, j0, j1; float wi0, wi1, wj0, wj1;
        if (I & 1) { i0 = I >> 1; wi0 = 0.75f; i1 = min(i0 + 1, 31); wi1 = 0.25f; }
        else       { i1 = I >> 1; wi1 = 0.75f; i0 = max(i1 - 1, 0);  wi0 = 0.25f; }
        if (J & 1) { j0 = J >> 1; wj0 = 0.75f; j1 = min(j0 + 1, 31); wj1 = 0.25f; }
        else       { j1 = J >> 1; wj1 = 0.75f; j0 = max(j1 - 1, 0);  wj0 = 0.25f; }
        xo[idx] += wi0 * (wj0 * vpe[i0 * 32 + j0] + wj1 * vpe[i0 * 32 + j1])
                 + wi1 * (wj0 * vpe[i1 * 32 + j0] + wj1 * vpe[i1 * 32 + j1]);
    }
}

extern "C" void kernel_launch(void* const* d_in, const int* in_sizes, int n_in,
                              void* d_out, int out_size)
{
    const float* x      = (const float*)d_in[0];
    const float* upper  = (const float*)d_in[1];
    const float* q_w    = (const float*)d_in[2];
    const float* q_b    = (const float*)d_in[3];
    const float* kv_w   = (const float*)d_in[4];
    const float* kv_b   = (const float*)d_in[5];
    const float* proj_w = (const float*)d_in[6];
    const float* proj_b = (const float*)d_in[7];
    const float* pe_w   = (const float*)d_in[8];
    const float* pe_b   = (const float*)d_in[9];
    const float* gate_w = (const float*)d_in[10];
    const float* gate_b = (const float*)d_in[11];
    float* out = (float*)d_out;

    cudaFuncSetAttribute(attn_kernel, cudaFuncAttributeMaxDynamicSharedMemorySize,
                         ATTN_SMEM_FLOATS * 4);

    gemm_kernel<<<dim3(32, 6, 2), 256>>>(x, q_w, q_b, kv_w, kv_b, nullptr, NQ, 0);
    gemm_kernel<<<dim3(8, 4, 2), 256>>>(upper, kv_w, kv_b, nullptr, nullptr, nullptr, NU, 1);
    topk_kernel<<<16, 256>>>();
    attn_kernel<<<dim3(64, 16), 128, ATTN_SMEM_FLOATS * 4>>>(gate_w, gate_b);
    dwupadd_kernel<<<BATCH * DIM, 256>>>(pe_w, pe_b);
    gemm_kernel<<<dim3(32, 2, 2), 256>>>(nullptr, proj_w, proj_b, nullptr, nullptr, out, NQ, 2);
}

// round 12
// speedup vs baseline: 1.0152x; 1.0152x over previous
#include <cuda_runtime.h>
#include <math.h>
#include <stdint.h>

#define BATCH 2
#define DIM 256
#define HEADS 8
#define NQ 4096
#define NU 1024
#define TOPK 4
#define NTK 16
#define ATT_SCALE 0.17677669529663687f

typedef unsigned long long u64;

__device__ __forceinline__ u64 dup2(float a) {
    u64 r; asm("mov.b64 %0, {%1, %1};" : "=l"(r) : "f"(a)); return r;
}
__device__ __forceinline__ void fma2(u64& d, u64 a, u64 b) {
    asm("fma.rn.f32x2 %0, %1, %2, %3;" : "=l"(d) : "l"(a), "l"(b), "l"(d));
}
__device__ __forceinline__ float2 unpk2(u64 v) {
    float2 r; asm("mov.b64 {%0, %1}, %2;" : "=f"(r.x), "=f"(r.y) : "l"(v)); return r;
}

__device__ float g_qT [BATCH*HEADS*32*NQ];
__device__ float g_fkT[BATCH*HEADS*32*NQ];
__device__ float g_fvT[BATCH*HEADS*32*NQ];
__device__ float g_kT [BATCH*HEADS*32*NU];
__device__ float g_v  [BATCH*HEADS*NU*32];
__device__ float g_vt [BATCH*DIM*NU];
__device__ float g_xout[BATCH*DIM*NQ];
__device__ int   g_txi[16*NTK];

__device__ __forceinline__ void threefry2x32_k42(uint32_t x0, uint32_t x1,
                                                 uint32_t& o0, uint32_t& o1) {
    const uint32_t ks1 = 42u, ks2 = 42u ^ 0x1BD11BDAu;
    x1 += ks1;
#define TF_R(r) { x0 += x1; x1 = (x1 << (r)) | (x1 >> (32 - (r))); x1 ^= x0; }
    TF_R(13) TF_R(15) TF_R(26) TF_R(6)
    x0 += ks1; x1 += ks2 + 1u;
    TF_R(17) TF_R(29) TF_R(16) TF_R(24)
    x0 += ks2; x1 += 2u;
    TF_R(13) TF_R(15) TF_R(26) TF_R(6)
    x0 += 0u; x1 += ks1 + 3u;
    TF_R(17) TF_R(29) TF_R(16) TF_R(24)
    x0 += ks1; x1 += ks2 + 4u;
    TF_R(13) TF_R(15) TF_R(26) TF_R(6)
    x0 += ks2; x1 += 5u;
#undef TF_R
    o0 = x0; o1 = x1;
}

__device__ __forceinline__ float gumbel_at(uint32_t l) {
    uint32_t o0, o1;
    threefry2x32_k42(0u, l, o0, o1);
    uint32_t bits = o0 ^ o1;
    float u01 = __uint_as_float((bits >> 9) | 0x3F800000u) - 1.0f;
    const float TINY = 1.17549435e-38f;
    float u = fmaxf(TINY, u01 * (1.0f - TINY) + TINY);
    return -logf(-logf(u));
}

// ---------------- GEMM 128x128, 8x8 microtile, f32x2 ------------------------
__global__ void __launch_bounds__(256, 2)
gemm_kernel(const float* __restrict__ X,
            const float* __restrict__ W1, const float* __restrict__ B1,
            const float* __restrict__ W2, const float* __restrict__ B2,
            float* __restrict__ dst, int P, int mode)
{
    __shared__ float Xs[2][8][128];
    __shared__ float Wt[2][8][132];
    const int b = blockIdx.z, p0 = blockIdx.x * 128, o0 = blockIdx.y * 128;
    const int t = threadIdx.x, to = t >> 4, tp = t & 15;
    const int xc = t >> 5, xp4 = t & 31, woo = t >> 1, whalf = t & 1;

    const float* Xb = (mode == 2) ? (g_xout + (long)b * DIM * P) : (X + (long)b * DIM * P);
    int ow = o0 + woo;
    const float* wptr = (mode == 0 && ow >= 256) ? W2 + (ow - 256) * DIM : W1 + ow * DIM;

    float4 xr = *(const float4*)&Xb[(long)xc * P + p0 + xp4 * 4];
    float4 wr = *(const float4*)&wptr[whalf * 4];

    u64 acc2[8][4];
#pragma unroll
    for (int i = 0; i < 8; i++)
#pragma unroll
        for (int j = 0; j < 4; j++) acc2[i][j] = 0ULL;

    int buf = 0;
    for (int c0 = 0; c0 < DIM; c0 += 8) {
        *(float4*)&Xs[buf][xc][xp4 * 4] = xr;
        Wt[buf][whalf * 4 + 0][woo] = wr.x;
        Wt[buf][whalf * 4 + 1][woo] = wr.y;
        Wt[buf][whalf * 4 + 2][woo] = wr.z;
        Wt[buf][whalf * 4 + 3][woo] = wr.w;
        __syncthreads();
        if (c0 + 8 < DIM) {
            xr = *(const float4*)&Xb[(long)(c0 + 8 + xc) * P + p0 + xp4 * 4];
            wr = *(const float4*)&wptr[c0 + 8 + whalf * 4];
        }
#pragma unroll
        for (int k = 0; k < 8; k++) {
            float4 a0 = *(const float4*)&Wt[buf][k][to * 8];
            float4 a1 = *(const float4*)&Wt[buf][k][to * 8 + 4];
            ulonglong2 xl = *(const ulonglong2*)&Xs[buf][k][tp * 8];
            ulonglong2 xh = *(const ulonglong2*)&Xs[buf][k][tp * 8 + 4];
            u64 xp[4] = {xl.x, xl.y, xh.x, xh.y};
            float av[8] = {a0.x, a0.y, a0.z, a0.w, a1.x, a1.y, a1.z, a1.w};
#pragma unroll
            for (int i = 0; i < 8; i++) {
                u64 ad = dup2(av[i]);
#pragma unroll
                for (int j = 0; j < 4; j++) fma2(acc2[i][j], ad, xp[j]);
            }
        }
        buf ^= 1;
    }

    const int p = p0 + tp * 8;
#pragma unroll
    for (int i = 0; i < 8; i++) {
        int o = o0 + to * 8 + i;
        float bias = (mode == 0 && o >= 256) ? B2[o - 256] : B1[o];
        float r[8];
#pragma unroll
        for (int j = 0; j < 4; j++) {
            float2 f = unpk2(acc2[i][j]);
            r[j * 2] = f.x + bias; r[j * 2 + 1] = f.y + bias;
        }
        if (mode == 0) {
            if (o < 256) {
#pragma unroll
                for (int j = 0; j < 8; j++) r[j] *= ATT_SCALE;
                float* ptr = g_qT + ((long)(b * 8 + (o >> 5)) * 32 + (o & 31)) * NQ + p;
                *(float4*)&ptr[0] = make_float4(r[0], r[1], r[2], r[3]);
                *(float4*)&ptr[4] = make_float4(r[4], r[5], r[6], r[7]);
            } else {
                int e2 = o - 256, h = e2 >> 6, e = e2 & 63;
                float* base = (e < 32) ? g_fkT : g_fvT;
                float* ptr = base + ((long)(b * 8 + h) * 32 + (e & 31)) * NQ + p;
                *(float4*)&ptr[0] = make_float4(r[0], r[1], r[2], r[3]);
                *(float4*)&ptr[4] = make_float4(r[4], r[5], r[6], r[7]);
            }
        } else if (mode == 1) {
            int h = o >> 6, e = o & 63;
            if (e < 32) {
                float* ptr = g_kT + ((long)(b * 8 + h) * 32 + e) * NU + p;
                *(float4*)&ptr[0] = make_float4(r[0], r[1], r[2], r[3]);
                *(float4*)&ptr[4] = make_float4(r[4], r[5], r[6], r[7]);
            } else {
                int d = e - 32;
#pragma unroll
                for (int j = 0; j < 8; j++)
                    g_v[((long)(b * 8 + h) * NU + p + j) * 32 + d] = r[j];
                float* ptr = g_vt + ((long)(b * 256 + h * 32 + d)) * NU + p;
                *(float4*)&ptr[0] = make_float4(r[0], r[1], r[2], r[3]);
                *(float4*)&ptr[4] = make_float4(r[4], r[5], r[6], r[7]);
            }
        } else {
            float* ptr = dst + ((long)(b * 256 + o)) * NQ + p;
            *(float4*)&ptr[0] = make_float4(r[0], r[1], r[2], r[3]);
            *(float4*)&ptr[4] = make_float4(r[4], r[5], r[6], r[7]);
        }
    }
}

// ---------------- topk --------------------------------------------------------
__global__ void __launch_bounds__(256) topk_kernel() {
    const int bh = blockIdx.x, t = threadIdx.x, w = t >> 5, l = t & 31;
    __shared__ float qm[32], cv[32];
    __shared__ int ci[32], sel[TOPK];
    const float* qb = g_qT + (long)bh * 32 * NQ;
#pragma unroll
    for (int dd = 0; dd < 4; dd++) {
        int d = w * 4 + dd;
        float s = 0.0f;
        const float* row = qb + (long)d * NQ;
        for (int i = l; i < NQ; i += 32) s += row[i];
#pragma unroll
        for (int off = 16; off >= 1; off >>= 1) s += __shfl_xor_sync(~0u, s, off);
        if (l == 0) qm[d] = s * (1.0f / NQ);
    }
    __syncthreads();
    const float* kb = g_kT + (long)bh * 32 * NU;
    float v[4]; int id[4];
#pragma unroll
    for (int r = 0; r < 4; r++) {
        int m = t + r * 256;
        float s = 0.0f;
#pragma unroll
        for (int d = 0; d < 32; d++) s += qm[d] * kb[d * NU + m];
        v[r] = s + gumbel_at((uint32_t)(bh * NU + m));
        id[r] = m;
    }
#pragma unroll
    for (int it = 0; it < TOPK; it++) {
        float lv = v[0]; int li = id[0];
#pragma unroll
        for (int r = 1; r < 4; r++) if (v[r] > lv) { lv = v[r]; li = id[r]; }
#pragma unroll
        for (int off = 16; off >= 1; off >>= 1) {
            float ov = __shfl_xor_sync(~0u, lv, off);
            int oi = __shfl_xor_sync(~0u, li, off);
            if (ov > lv) { lv = ov; li = oi; }
        }
#pragma unroll
        for (int r = 0; r < 4; r++) if (id[r] == li) v[r] = -INFINITY;
        if (l == 0) { cv[w * 4 + it] = lv; ci[w * 4 + it] = li; }
    }
    __syncthreads();
    if (t < 32) {
        float lv = cv[t]; int li = ci[t];
#pragma unroll
        for (int it = 0; it < TOPK; it++) {
            float bv = lv; int bi = li;
#pragma unroll
            for (int off = 16; off >= 1; off >>= 1) {
                float ov = __shfl_xor_sync(~0u, bv, off);
                int oi = __shfl_xor_sync(~0u, bi, off);
                if (ov > bv) { bv = ov; bi = oi; }
            }
            if (li == bi) lv = -INFINITY;
            if (t == 0) sel[it] = bi;
        }
    }
    __syncthreads();
    if (t < NTK) {
        int grp = t / TOPK, kk = t % TOPK;
        int m = sel[kk];
        g_txi[bh * NTK + t] = ((m >> 5) * 2 + (grp >> 1)) * 64 + (m & 31) * 2 + (grp & 1);
    }
}

// ---------------- attention: q64, m-chunk 64, 128 thr, 4 blocks/SM ----------
#define OFF_QT  0        // [32][68]
#define OFF_KT  2176     // [32][64]
#define OFF_VS  4224     // [64][32]
#define OFF_PX  6272     // P[64][64] during mainloop
#define OA_BASE 6528     // OA[2][64][32] (offset from P base avoids OUT race)
#define OFF_LR  10624
#define OFF_TXI 10688    // int[16]
// fine-phase overlays
#define OFF_OUT 2176     // [64][68] -> ends 6528 (KT+VS+P-pad, all dead)
#define OFF_TK  6528     // [16][32] (overlays dead OA after reduce)
#define OFF_TV  7040     // [16][32]
#define OFF_GS  7552     // [32][64]
#define OFF_GB  9600     // [32]
#define OFF_SC  9632     // [64][17] -> ends 10720
#define ATTN_SMEM_FLOATS 10720

__global__ void __launch_bounds__(128, 4)
attn_kernel(const float* __restrict__ gate_w, const float* __restrict__ gate_b)
{
    extern __shared__ float sm[];
    const int bh = blockIdx.y, n0 = blockIdx.x * 64, t = threadIdx.x;
    const int b = bh >> 3, h = bh & 7;
    const int qg = t >> 3, mg = t & 7;                       // QK: 16 qg x 8 mg
    const int ms = t >> 6, qg2 = (t >> 2) & 15, dg = t & 3;  // AV: 2 ms x 16 q x 4 dg

    const float* kb = g_kT + (long)bh * 32 * NU;
    const float* vb = g_v  + (long)bh * NU * 32;

    const float* qb = g_qT + (long)bh * 32 * NQ + n0;
#pragma unroll
    for (int r = 0; r < 4; r++) {
        int f4 = t + r * 128;
        int d = f4 >> 4, qf = (f4 & 15) << 2;
        *(float4*)&sm[OFF_QT + d * 68 + qf] = *(const float4*)&qb[(long)d * NQ + qf];
    }
    if (t < NTK) ((int*)sm)[OFF_TXI + t] = g_txi[bh * NTK + t];

    u64 acc2[4][4];
    float runl[4];
#pragma unroll
    for (int i = 0; i < 4; i++) {
        runl[i] = 0.0f;
#pragma unroll
        for (int j = 0; j < 4; j++) acc2[i][j] = 0ULL;
    }

    const int slA = ((qg + mg) & 15) * 4, slB = ((qg + mg + 8) & 15) * 4;

    for (int it = 0; it < 16; it++) {
        const int m0 = it * 64;
        __syncthreads();   // prev AV done: KT/VS/P free
        // stage KT (rotated) + VS
#pragma unroll
        for (int r = 0; r < 4; r++) {
            int idx = t + r * 128;          // 512 float4
            int k = idx >> 4, c = idx & 15;
            *(float4*)&sm[OFF_KT + k * 64 + ((c + k) & 15) * 4] =
                *(const float4*)&kb[(long)k * NU + m0 + c * 4];
            *(float4*)&sm[OFF_VS + idx * 4] = *(const float4*)&vb[(long)m0 * 32 + idx * 4];
        }
        __syncthreads();

        // ---- QK 4q x 8m ----
        u64 s2[4][4];
#pragma unroll
        for (int i = 0; i < 4; i++)
#pragma unroll
            for (int j = 0; j < 4; j++) s2[i][j] = 0ULL;
#pragma unroll 4
        for (int k = 0; k < 32; k++) {
            float4 qa = *(const float4*)&sm[OFF_QT + k * 68 + qg * 4];
            ulonglong2 k0 = *(const ulonglong2*)&sm[OFF_KT + k * 64 + ((mg + k) & 15) * 4];
            ulonglong2 k1 = *(const ulonglong2*)&sm[OFF_KT + k * 64 + ((mg + 8 + k) & 15) * 4];
            u64 kp[4] = {k0.x, k0.y, k1.x, k1.y};
            float qv[4] = {qa.x, qa.y, qa.z, qa.w};
#pragma unroll
            for (int i = 0; i < 4; i++) {
                u64 qd = dup2(qv[i]);
#pragma unroll
                for (int j = 0; j < 4; j++) fma2(s2[i][j], qd, kp[j]);
            }
        }
        // exp + transposed P store
        float e[4][8];
#pragma unroll
        for (int i = 0; i < 4; i++)
#pragma unroll
            for (int j = 0; j < 4; j++) {
                float2 f = unpk2(s2[i][j]);
                e[i][j * 2]     = __expf(f.x);
                e[i][j * 2 + 1] = __expf(f.y);
                runl[i] += e[i][j * 2] + e[i][j * 2 + 1];
            }
#pragma unroll
        for (int j = 0; j < 4; j++) {
            int mA = mg * 4 + j, mB = 32 + mg * 4 + j;
            *(float4*)&sm[OFF_PX + mA * 64 + slA] =
                make_float4(e[0][j], e[1][j], e[2][j], e[3][j]);
            *(float4*)&sm[OFF_PX + mB * 64 + slB] =
                make_float4(e[0][4 + j], e[1][4 + j], e[2][4 + j], e[3][4 + j]);
        }
        __syncthreads();

        // ---- AV 4q x 8d, 2-way m-split ----
#pragma unroll 4
        for (int st = 0; st < 32; st++) {
            int m = ms * 32 + st;
            int sl = ((qg2 + (m >> 2)) & 15) * 4;
            float4 p = *(const float4*)&sm[OFF_PX + m * 64 + sl];
            ulonglong2 v0 = *(const ulonglong2*)&sm[OFF_VS + m * 32 + dg * 8];
            ulonglong2 v1 = *(const ulonglong2*)&sm[OFF_VS + m * 32 + dg * 8 + 4];
            u64 vp[4] = {v0.x, v0.y, v1.x, v1.y};
            float pv[4] = {p.x, p.y, p.z, p.w};
#pragma unroll
            for (int i = 0; i < 4; i++) {
                u64 pd = dup2(pv[i]);
#pragma unroll
                for (int j = 0; j < 4; j++) fma2(acc2[i][j], pd, vp[j]);
            }
        }
    }

    // row sums over mg (lane bits 0..2)
#pragma unroll
    for (int i = 0; i < 4; i++) {
        float r = runl[i];
        r += __shfl_xor_sync(~0u, r, 4, 8);
        r += __shfl_xor_sync(~0u, r, 2, 8);
        r += __shfl_xor_sync(~0u, r, 1, 8);
        if (mg == 0) sm[OFF_LR + qg * 4 + i] = r;
    }
    __syncthreads();   // AV done everywhere; LR visible

    // park AV partials OA[ms][q][32]
#pragma unroll
    for (int i = 0; i < 4; i++) {
        int q = qg2 * 4 + i;
        int base = OA_BASE + (ms * 64 + q) * 32 + dg * 8;
        float2 f0 = unpk2(acc2[i][0]), f1 = unpk2(acc2[i][1]);
        float2 f2 = unpk2(acc2[i][2]), f3 = unpk2(acc2[i][3]);
        *(float4*)&sm[base]     = make_float4(f0.x, f0.y, f1.x, f1.y);
        *(float4*)&sm[base + 4] = make_float4(f2.x, f2.y, f3.x, f3.y);
    }
    __syncthreads();

    // reduce -> coarse Out[q][d]
#pragma unroll
    for (int r = 0; r < 16; r++) {
        int idx = t + r * 128;
        int q = idx >> 5, d = idx & 31;
        float c = sm[OA_BASE + q * 32 + d] + sm[OA_BASE + 2048 + q * 32 + d];
        sm[OFF_OUT + q * 68 + d] = c / sm[OFF_LR + q];
    }
    __syncthreads();

    // gather fine K/V (overlays dead OA) + gate weights
#pragma unroll
    for (int r = 0; r < 4; r++) {
        int idx = t + r * 128;
        int kk = idx >> 5, d = idx & 31;
        int m = ((int*)sm)[OFF_TXI + kk];
        sm[OFF_TK + kk * 32 + d] = g_fkT[((long)bh * 32 + d) * NQ + m];
        sm[OFF_TV + kk * 32 + d] = g_fvT[((long)bh * 32 + d) * NQ + m];
    }
#pragma unroll
    for (int r = 0; r < 16; r++) sm[OFF_GS + t + r * 128] = gate_w[t + r * 128];
    if (t < 32) sm[OFF_GB + t] = gate_b[t];
    __syncthreads();

    // fine scores (q = t>>1, 8 keys each)
    {
        const int q = t >> 1, kg = t & 1;
        float qv[32];
#pragma unroll
        for (int d = 0; d < 32; d++) qv[d] = sm[OFF_QT + d * 68 + q];
#pragma unroll
        for (int j = 0; j < 8; j++) {
            int kk = kg * 8 + j;
            float s = 0.0f;
#pragma unroll
            for (int d = 0; d < 32; d++) s += qv[d] * sm[OFF_TK + kk * 32 + d];
            sm[OFF_SC + q * 17 + kk] = __expf(s);
        }
    }
    __syncthreads();
    if (t < 64) {
        float sum = 0.0f;
#pragma unroll
        for (int kk = 0; kk < NTK; kk++) sum += sm[OFF_SC + t * 17 + kk];
        sm[OFF_SC + t * 17 + 16] = 1.0f / sum;
    }
    __syncthreads();
    // refined (q = t>>1, 16 d each)
    {
        const int q = t >> 1, hf = t & 1;
        float inv = sm[OFF_SC + q * 17 + 16];
        float sc[NTK];
#pragma unroll
        for (int kk = 0; kk < NTK; kk++) sc[kk] = sm[OFF_SC + q * 17 + kk];
#pragma unroll
        for (int dd = 0; dd < 16; dd++) {
            int d = hf * 16 + dd;
            float r = 0.0f;
#pragma unroll
            for (int kk = 0; kk < NTK; kk++) r += sc[kk] * sm[OFF_TV + kk * 32 + d];
            sm[OFF_OUT + q * 68 + 32 + d] = r * inv;
        }
    }
    __syncthreads();
    // gate + combine (q = t>>1, 16 d each)
    {
        const int q = t >> 1, hf = t & 1;
        float ov[64];
#pragma unroll
        for (int c4 = 0; c4 < 16; c4++)
            *(float4*)&ov[c4 * 4] = *(const float4*)&sm[OFF_OUT + q * 68 + c4 * 4];
        float res[16];
#pragma unroll
        for (int dd = 0; dd < 16; dd++) {
            int d = hf * 16 + dd;
            float g = sm[OFF_GB + d];
#pragma unroll
            for (int c = 0; c < 64; c++) g += ov[c] * sm[OFF_GS + d * 64 + c];
            float gv = 1.0f / (1.0f + __expf(-g));
            res[dd] = gv * sm[OFF_OUT + q * 68 + 32 + d] + (1.0f - gv) * ov[d];
        }
        __syncthreads();
#pragma unroll
        for (int dd = 0; dd < 16; dd++)
            sm[OFF_OUT + q * 68 + hf * 16 + dd] = res[dd];
    }
    __syncthreads();

    float* xo = g_xout + ((long)(b * 256 + h * 32)) * NQ + n0;
#pragma unroll
    for (int r = 0; r < 16; r++) {
        int idx = t + r * 128;
        int d = idx >> 6, q = idx & 63;
        xo[(long)d * NQ + q] = sm[OFF_OUT + q * 68 + d];
    }
}

// ---------------- depthwise 7x7 + bilinear up + add -------------------------
__global__ void __launch_bounds__(256)
dwupadd_kernel(const float* __restrict__ pe_w, const float* __restrict__ pe_b)
{
    int bc = blockIdx.x, t = threadIdx.x;
    __shared__ float tile[38 * 38], wv[49], vpe[1024];
    const float* src = g_vt + (long)bc * NU;
    for (int idx = t; idx < 38 * 38; idx += 256) {
        int ii = idx / 38 - 3, jj = idx % 38 - 3;
        tile[idx] = (ii >= 0 && ii < 32 && jj >= 0 && jj < 32) ? src[ii * 32 + jj] : 0.0f;
    }
    int c = bc & 255;
    if (t < 49) wv[t] = pe_w[c * 49 + t];
    __syncthreads();
    float bias = pe_b[c];
    for (int idx = t; idx < NU; idx += 256) {
        int i = idx >> 5, j = idx & 31;
        float s = bias;
#pragma unroll
        for (int di = 0; di < 7; di++)
#pragma unroll
            for (int dj = 0; dj < 7; dj++)
                s += tile[(i + di) * 38 + (j + dj)] * wv[di * 7 + dj];
        vpe[idx] = s;
    }
    __syncthreads();
    float* xo = g_xout + (long)bc * NQ;
    for (int idx = t; idx < NQ; idx += 256) {
        int I = idx >> 6, J = idx & 63;
        int i0, i1, j0, j1; float wi0, wi1, wj0, wj1;
        if (I & 1) { i0 = I >> 1; wi0 = 0.75f; i1 = min(i0 + 1, 31); wi1 = 0.25f; }
        else       { i1 = I >> 1; wi1 = 0.75f; i0 = max(i1 - 1, 0);  wi0 = 0.25f; }
        if (J & 1) { j0 = J >> 1; wj0 = 0.75f; j1 = min(j0 + 1, 31); wj1 = 0.25f; }
        else       { j1 = J >> 1; wj1 = 0.75f; j0 = max(j1 - 1, 0);  wj0 = 0.25f; }
        xo[idx] += wi0 * (wj0 * vpe[i0 * 32 + j0] + wj1 * vpe[i0 * 32 + j1])
                 + wi1 * (wj0 * vpe[i1 * 32 + j0] + wj1 * vpe[i1 * 32 + j1]);
    }
}

extern "C" void kernel_launch(void* const* d_in, const int* in_sizes, int n_in,
                              void* d_out, int out_size)
{
    const float* x      = (const float*)d_in[0];
    const float* upper  = (const float*)d_in[1];
    const float* q_w    = (const float*)d_in[2];
    const float* q_b    = (const float*)d_in[3];
    const float* kv_w   = (const float*)d_in[4];
    const float* kv_b   = (const float*)d_in[5];
    const float* proj_w = (const float*)d_in[6];
    const float* proj_b = (const float*)d_in[7];
    const float* pe_w   = (const float*)d_in[8];
    const float* pe_b   = (const float*)d_in[9];
    const float* gate_w = (const float*)d_in[10];
    const float* gate_b = (const float*)d_in[11];
    float* out = (float*)d_out;

    cudaFuncSetAttribute(attn_kernel, cudaFuncAttributeMaxDynamicSharedMemorySize,
                         ATTN_SMEM_FLOATS * 4);

    gemm_kernel<<<dim3(32, 6, 2), 256>>>(x, q_w, q_b, kv_w, kv_b, nullptr, NQ, 0);
    gemm_kernel<<<dim3(8, 4, 2), 256>>>(upper, kv_w, kv_b, nullptr, nullptr, nullptr, NU, 1);
    topk_kernel<<<16, 256>>>();
    attn_kernel<<<dim3(64, 16), 128, ATTN_SMEM_FLOATS * 4>>>(gate_w, gate_b);
    dwupadd_kernel<<<BATCH * DIM, 256>>>(pe_w, pe_b);
    gemm_kernel<<<dim3(32, 2, 2), 256>>>(nullptr, proj_w, proj_b, nullptr, nullptr, out, NQ, 2);
}

// round 13
// speedup vs baseline: 1.1757x; 1.1580x over previous
#include <cuda_runtime.h>
#include <math.h>
#include <stdint.h>

#define BATCH 2
#define DIM 256
#define HEADS 8
#define NQ 4096
#define NU 1024
#define TOPK 4
#define NTK 16
#define ATT_SCALE 0.17677669529663687f

typedef unsigned long long u64;

__device__ __forceinline__ u64 dup2(float a) {
    u64 r; asm("mov.b64 %0, {%1, %1};" : "=l"(r) : "f"(a)); return r;
}
__device__ __forceinline__ void fma2(u64& d, u64 a, u64 b) {
    asm("fma.rn.f32x2 %0, %1, %2, %3;" : "=l"(d) : "l"(a), "l"(b), "l"(d));
}
__device__ __forceinline__ float2 unpk2(u64 v) {
    float2 r; asm("mov.b64 {%0, %1}, %2;" : "=f"(r.x), "=f"(r.y) : "l"(v)); return r;
}

__device__ float g_qT [BATCH*HEADS*32*NQ];
__device__ float g_fkT[BATCH*HEADS*32*NQ];
__device__ float g_fvT[BATCH*HEADS*32*NQ];
__device__ float g_kT [BATCH*HEADS*32*NU];
__device__ float g_v  [BATCH*HEADS*NU*32];
__device__ float g_vt [BATCH*DIM*NU];
__device__ float g_xout[BATCH*DIM*NQ];
__device__ float g_qpart[16*8*32];
__device__ int   g_txi[16*NTK];

__device__ __forceinline__ void threefry2x32_k42(uint32_t x0, uint32_t x1,
                                                 uint32_t& o0, uint32_t& o1) {
    const uint32_t ks1 = 42u, ks2 = 42u ^ 0x1BD11BDAu;
    x1 += ks1;
#define TF_R(r) { x0 += x1; x1 = (x1 << (r)) | (x1 >> (32 - (r))); x1 ^= x0; }
    TF_R(13) TF_R(15) TF_R(26) TF_R(6)
    x0 += ks1; x1 += ks2 + 1u;
    TF_R(17) TF_R(29) TF_R(16) TF_R(24)
    x0 += ks2; x1 += 2u;
    TF_R(13) TF_R(15) TF_R(26) TF_R(6)
    x0 += 0u; x1 += ks1 + 3u;
    TF_R(17) TF_R(29) TF_R(16) TF_R(24)
    x0 += ks1; x1 += ks2 + 4u;
    TF_R(13) TF_R(15) TF_R(26) TF_R(6)
    x0 += ks2; x1 += 5u;
#undef TF_R
    o0 = x0; o1 = x1;
}

__device__ __forceinline__ float gumbel_at(uint32_t l) {
    uint32_t o0, o1;
    threefry2x32_k42(0u, l, o0, o1);
    uint32_t bits = o0 ^ o1;
    float u01 = __uint_as_float((bits >> 9) | 0x3F800000u) - 1.0f;
    const float TINY = 1.17549435e-38f;
    float u = fmaxf(TINY, u01 * (1.0f - TINY) + TINY);
    return -logf(-logf(u));
}

// ------------- combined GEMM for q/fkv (x) and k/v (upper): 448 blocks ------
__global__ void __launch_bounds__(256, 2)
gemm01_kernel(const float* __restrict__ x, const float* __restrict__ upper,
              const float* __restrict__ q_w, const float* __restrict__ q_b,
              const float* __restrict__ kv_w, const float* __restrict__ kv_b)
{
    __shared__ float Xs[2][8][128];
    __shared__ float Wt[2][8][132];
    int id = blockIdx.x;
    int sub, b, o0, p0, P;
    const float* Xb;
    if (id < 384) {
        sub = 0; b = id / 192; int r = id % 192;
        o0 = (r / 32) * 128; p0 = (r % 32) * 128; P = NQ;
        Xb = x + (long)b * DIM * NQ;
    } else {
        id -= 384;
        sub = 1; b = id / 32; int r = id % 32;
        o0 = (r / 8) * 128; p0 = (r % 8) * 128; P = NU;
        Xb = upper + (long)b * DIM * NU;
    }
    const int t = threadIdx.x, to = t >> 4, tp = t & 15;
    const int xc = t >> 5, xp4 = t & 31, woo = t >> 1, whalf = t & 1;

    int ow = o0 + woo;
    const float* wptr = (sub == 0 && ow < 256) ? q_w + ow * DIM
                        : kv_w + ((sub == 0) ? (ow - 256) : ow) * DIM;

    float4 xr = *(const float4*)&Xb[(long)xc * P + p0 + xp4 * 4];
    float4 wr = *(const float4*)&wptr[whalf * 4];

    u64 acc2[8][4];
#pragma unroll
    for (int i = 0; i < 8; i++)
#pragma unroll
        for (int j = 0; j < 4; j++) acc2[i][j] = 0ULL;

    int buf = 0;
    for (int c0 = 0; c0 < DIM; c0 += 8) {
        *(float4*)&Xs[buf][xc][xp4 * 4] = xr;
        Wt[buf][whalf * 4 + 0][woo] = wr.x;
        Wt[buf][whalf * 4 + 1][woo] = wr.y;
        Wt[buf][whalf * 4 + 2][woo] = wr.z;
        Wt[buf][whalf * 4 + 3][woo] = wr.w;
        __syncthreads();
        if (c0 + 8 < DIM) {
            xr = *(const float4*)&Xb[(long)(c0 + 8 + xc) * P + p0 + xp4 * 4];
            wr = *(const float4*)&wptr[c0 + 8 + whalf * 4];
        }
#pragma unroll
        for (int k = 0; k < 8; k++) {
            float4 a0 = *(const float4*)&Wt[buf][k][to * 8];
            float4 a1 = *(const float4*)&Wt[buf][k][to * 8 + 4];
            ulonglong2 xl = *(const ulonglong2*)&Xs[buf][k][tp * 8];
            ulonglong2 xh = *(const ulonglong2*)&Xs[buf][k][tp * 8 + 4];
            u64 xp[4] = {xl.x, xl.y, xh.x, xh.y};
            float av[8] = {a0.x, a0.y, a0.z, a0.w, a1.x, a1.y, a1.z, a1.w};
#pragma unroll
            for (int i = 0; i < 8; i++) {
                u64 ad = dup2(av[i]);
#pragma unroll
                for (int j = 0; j < 4; j++) fma2(acc2[i][j], ad, xp[j]);
            }
        }
        buf ^= 1;
    }

    const int p = p0 + tp * 8;
#pragma unroll
    for (int i = 0; i < 8; i++) {
        int o = o0 + to * 8 + i;
        float bias = (sub == 0 && o < 256) ? q_b[o]
                     : kv_b[(sub == 0) ? (o - 256) : o];
        float r[8];
#pragma unroll
        for (int j = 0; j < 4; j++) {
            float2 f = unpk2(acc2[i][j]);
            r[j * 2] = f.x + bias; r[j * 2 + 1] = f.y + bias;
        }
        if (sub == 0) {
            if (o < 256) {
#pragma unroll
                for (int j = 0; j < 8; j++) r[j] *= ATT_SCALE;
                float* ptr = g_qT + ((long)(b * 8 + (o >> 5)) * 32 + (o & 31)) * NQ + p;
                *(float4*)&ptr[0] = make_float4(r[0], r[1], r[2], r[3]);
                *(float4*)&ptr[4] = make_float4(r[4], r[5], r[6], r[7]);
            } else {
                int e2 = o - 256, h = e2 >> 6, e = e2 & 63;
                float* base = (e < 32) ? g_fkT : g_fvT;
                float* ptr = base + ((long)(b * 8 + h) * 32 + (e & 31)) * NQ + p;
                *(float4*)&ptr[0] = make_float4(r[0], r[1], r[2], r[3]);
                *(float4*)&ptr[4] = make_float4(r[4], r[5], r[6], r[7]);
            }
        } else {
            int h = o >> 6, e = o & 63;
            if (e < 32) {
                float* ptr = g_kT + ((long)(b * 8 + h) * 32 + e) * NU + p;
                *(float4*)&ptr[0] = make_float4(r[0], r[1], r[2], r[3]);
                *(float4*)&ptr[4] = make_float4(r[4], r[5], r[6], r[7]);
            } else {
                int d = e - 32;
#pragma unroll
                for (int j = 0; j < 8; j++)
                    g_v[((long)(b * 8 + h) * NU + p + j) * 32 + d] = r[j];
                float* ptr = g_vt + ((long)(b * 256 + h * 32 + d)) * NU + p;
                *(float4*)&ptr[0] = make_float4(r[0], r[1], r[2], r[3]);
                *(float4*)&ptr[4] = make_float4(r[4], r[5], r[6], r[7]);
            }
        }
    }
}

// ---------------- proj GEMM (mode2) ------------------------------------------
__global__ void __launch_bounds__(256, 2)
gemm2_kernel(const float* __restrict__ W1, const float* __restrict__ B1,
             float* __restrict__ dst)
{
    __shared__ float Xs[2][8][128];
    __shared__ float Wt[2][8][132];
    const int b = blockIdx.z, p0 = blockIdx.x * 128, o0 = blockIdx.y * 128;
    const int t = threadIdx.x, to = t >> 4, tp = t & 15;
    const int xc = t >> 5, xp4 = t & 31, woo = t >> 1, whalf = t & 1;
    const float* Xb = g_xout + (long)b * DIM * NQ;
    const float* wptr = W1 + (o0 + woo) * DIM;

    float4 xr = *(const float4*)&Xb[(long)xc * NQ + p0 + xp4 * 4];
    float4 wr = *(const float4*)&wptr[whalf * 4];

    u64 acc2[8][4];
#pragma unroll
    for (int i = 0; i < 8; i++)
#pragma unroll
        for (int j = 0; j < 4; j++) acc2[i][j] = 0ULL;

    int buf = 0;
    for (int c0 = 0; c0 < DIM; c0 += 8) {
        *(float4*)&Xs[buf][xc][xp4 * 4] = xr;
        Wt[buf][whalf * 4 + 0][woo] = wr.x;
        Wt[buf][whalf * 4 + 1][woo] = wr.y;
        Wt[buf][whalf * 4 + 2][woo] = wr.z;
        Wt[buf][whalf * 4 + 3][woo] = wr.w;
        __syncthreads();
        if (c0 + 8 < DIM) {
            xr = *(const float4*)&Xb[(long)(c0 + 8 + xc) * NQ + p0 + xp4 * 4];
            wr = *(const float4*)&wptr[c0 + 8 + whalf * 4];
        }
#pragma unroll
        for (int k = 0; k < 8; k++) {
            float4 a0 = *(const float4*)&Wt[buf][k][to * 8];
            float4 a1 = *(const float4*)&Wt[buf][k][to * 8 + 4];
            ulonglong2 xl = *(const ulonglong2*)&Xs[buf][k][tp * 8];
            ulonglong2 xh = *(const ulonglong2*)&Xs[buf][k][tp * 8 + 4];
            u64 xp[4] = {xl.x, xl.y, xh.x, xh.y};
            float av[8] = {a0.x, a0.y, a0.z, a0.w, a1.x, a1.y, a1.z, a1.w};
#pragma unroll
            for (int i = 0; i < 8; i++) {
                u64 ad = dup2(av[i]);
#pragma unroll
                for (int j = 0; j < 4; j++) fma2(acc2[i][j], ad, xp[j]);
            }
        }
        buf ^= 1;
    }

    const int p = p0 + tp * 8;
#pragma unroll
    for (int i = 0; i < 8; i++) {
        int o = o0 + to * 8 + i;
        float bias = B1[o];
        float r[8];
#pragma unroll
        for (int j = 0; j < 4; j++) {
            float2 f = unpk2(acc2[i][j]);
            r[j * 2] = f.x + bias; r[j * 2 + 1] = f.y + bias;
        }
        float* ptr = dst + ((long)(b * 256 + o)) * NQ + p;
        *(float4*)&ptr[0] = make_float4(r[0], r[1], r[2], r[3]);
        *(float4*)&ptr[4] = make_float4(r[4], r[5], r[6], r[7]);
    }
}

// ---------------- qmean partials: grid (8 slices, 16 bh) ---------------------
__global__ void __launch_bounds__(256) qpart_kernel() {
    const int s = blockIdx.x, bh = blockIdx.y;
    const int t = threadIdx.x;
    const int d = t >> 3, l8 = t & 7;
    const float* row = g_qT + ((long)bh * 32 + d) * NQ + s * 512 + l8 * 16;
    float sum = 0.0f;
#pragma unroll
    for (int i = 0; i < 4; i++) {
        float4 v0 = *(const float4*)&row[i * 128];
        float4 v1 = *(const float4*)&row[i * 128 + 4];
        float4 v2 = *(const float4*)&row[i * 128 + 8];
        float4 v3 = *(const float4*)&row[i * 128 + 12];
        sum += v0.x + v0.y + v0.z + v0.w + v1.x + v1.y + v1.z + v1.w
             + v2.x + v2.y + v2.z + v2.w + v3.x + v3.y + v3.z + v3.w;
    }
#pragma unroll
    for (int off = 4; off >= 1; off >>= 1)
        sum += __shfl_xor_sync(~0u, sum, off, 8);
    if (l8 == 0) g_qpart[(bh * 8 + s) * 32 + d] = sum;
}

// ---------------- topk --------------------------------------------------------
__global__ void __launch_bounds__(256) topk_kernel() {
    const int bh = blockIdx.x, t = threadIdx.x, w = t >> 5, l = t & 31;
    __shared__ float qm[32], cv[32];
    __shared__ int ci[32], sel[TOPK];
    if (t < 32) {
        float s = 0.0f;
#pragma unroll
        for (int i = 0; i < 8; i++) s += g_qpart[(bh * 8 + i) * 32 + t];
        qm[t] = s * (1.0f / NQ);
    }
    __syncthreads();
    const float* kb = g_kT + (long)bh * 32 * NU;
    float v[4]; int id[4];
#pragma unroll
    for (int r = 0; r < 4; r++) {
        int m = t + r * 256;
        float s = 0.0f;
#pragma unroll
        for (int d = 0; d < 32; d++) s += qm[d] * kb[d * NU + m];
        v[r] = s + gumbel_at((uint32_t)(bh * NU + m));
        id[r] = m;
    }
#pragma unroll
    for (int it = 0; it < TOPK; it++) {
        float lv = v[0]; int li = id[0];
#pragma unroll
        for (int r = 1; r < 4; r++) if (v[r] > lv) { lv = v[r]; li = id[r]; }
#pragma unroll
        for (int off = 16; off >= 1; off >>= 1) {
            float ov = __shfl_xor_sync(~0u, lv, off);
            int oi = __shfl_xor_sync(~0u, li, off);
            if (ov > lv) { lv = ov; li = oi; }
        }
#pragma unroll
        for (int r = 0; r < 4; r++) if (id[r] == li) v[r] = -INFINITY;
        if (l == 0) { cv[w * 4 + it] = lv; ci[w * 4 + it] = li; }
    }
    __syncthreads();
    if (t < 32) {
        float lv = cv[t]; int li = ci[t];
#pragma unroll
        for (int it = 0; it < TOPK; it++) {
            float bv = lv; int bi = li;
#pragma unroll
            for (int off = 16; off >= 1; off >>= 1) {
                float ov = __shfl_xor_sync(~0u, bv, off);
                int oi = __shfl_xor_sync(~0u, bi, off);
                if (ov > bv) { bv = ov; bi = oi; }
            }
            if (li == bi) lv = -INFINITY;
            if (t == 0) sel[it] = bi;
        }
    }
    __syncthreads();
    if (t < NTK) {
        int grp = t / TOPK, kk = t % TOPK;
        int m = sel[kk];
        g_txi[bh * NTK + t] = ((m >> 5) * 2 + (grp >> 1)) * 64 + (m & 31) * 2 + (grp & 1);
    }
}

// ---------------- attention (R8 exact): 128 thr, q64, m128, 3 blocks/SM -----
#define OFF_QT  0        // [32][68]
#define OFF_KT  2176     // [32][128]
#define OFF_VS  6272     // [128][32]
#define OFF_PX  10368    // P[128][64] / OA[4][64][32]
#define OFF_LR  18560
#define OFF_TXI 18624    // int[16]
#define ATTN_SMEM_FLOATS 18640
#define OFF_OUT 2176            // [64][68]
#define OFF_TK  6528            // [16][32]
#define OFF_TV  7040            // [16][32]
#define OFF_SC  7552            // [64][17]
#define OFF_GS  10368           // [32][64]
#define OFF_GB  12416           // [32]

__global__ void __launch_bounds__(128, 3)
attn_kernel(const float* __restrict__ gate_w, const float* __restrict__ gate_b)
{
    extern __shared__ float sm[];
    const int bh = blockIdx.y, n0 = blockIdx.x * 64, t = threadIdx.x;
    const int b = bh >> 3, h = bh & 7;
    const int qg = t >> 4, mg = t & 15;
    const int ms = t >> 5, qg2 = (t >> 2) & 7, dg = t & 3;

    const float* qb = g_qT + (long)bh * 32 * NQ + n0;
#pragma unroll
    for (int r = 0; r < 4; r++) {
        int f4 = t + r * 128;
        int d = f4 >> 4, qf = (f4 & 15) << 2;
        *(float4*)&sm[OFF_QT + d * 68 + qf] = *(const float4*)&qb[(long)d * NQ + qf];
    }
    if (t < NTK) ((int*)sm)[OFF_TXI + t] = g_txi[bh * NTK + t];

    u64 acc2[8][4];
    float runl[8];
#pragma unroll
    for (int i = 0; i < 8; i++) {
        runl[i] = 0.0f;
#pragma unroll
        for (int j = 0; j < 4; j++) acc2[i][j] = 0ULL;
    }

    const float* kb = g_kT + (long)bh * 32 * NU;
    const float* vb = g_v  + (long)bh * NU * 32;

    for (int m0 = 0; m0 < NU; m0 += 128) {
        __syncthreads();
#pragma unroll
        for (int r = 0; r < 8; r++) {
            int idx = t + r * 128;
            int d = idx >> 5, c2 = idx & 31;
            int sl = ((c2 >> 1) + ((c2 & 1) << 4) + d) & 31;
            *(float4*)&sm[OFF_KT + d * 128 + sl * 4] =
                *(const float4*)&kb[(long)d * NU + m0 + c2 * 4];
            *(float4*)&sm[OFF_VS + idx * 4] = *(const float4*)&vb[(long)m0 * 32 + idx * 4];
        }
        __syncthreads();

        u64 s2[8][4];
#pragma unroll
        for (int i = 0; i < 8; i++)
#pragma unroll
            for (int j = 0; j < 4; j++) s2[i][j] = 0ULL;
#pragma unroll 4
        for (int k = 0; k < 32; k++) {
            float4 qa = *(const float4*)&sm[OFF_QT + k * 68 + qg * 8];
            float4 qc = *(const float4*)&sm[OFF_QT + k * 68 + qg * 8 + 4];
            ulonglong2 k0 = *(const ulonglong2*)&sm[OFF_KT + k * 128 + ((mg + k) & 31) * 4];
            ulonglong2 k1 = *(const ulonglong2*)&sm[OFF_KT + k * 128 + ((mg + 16 + k) & 31) * 4];
            u64 kp[4] = {k0.x, k0.y, k1.x, k1.y};
            float qv[8] = {qa.x, qa.y, qa.z, qa.w, qc.x, qc.y, qc.z, qc.w};
#pragma unroll
            for (int i = 0; i < 8; i++) {
                u64 qd = dup2(qv[i]);
#pragma unroll
                for (int j = 0; j < 4; j++) fma2(s2[i][j], qd, kp[j]);
            }
        }
        float e[8][8];
#pragma unroll
        for (int i = 0; i < 8; i++)
#pragma unroll
            for (int j = 0; j < 4; j++) {
                float2 f = unpk2(s2[i][j]);
                e[i][j * 2]     = __expf(f.x);
                e[i][j * 2 + 1] = __expf(f.y);
                runl[i] += e[i][j * 2] + e[i][j * 2 + 1];
            }
        {
            int sl0 = ((qg + mg) & 15) * 4, sl1 = ((qg + 8 + mg) & 15) * 4;
#pragma unroll
            for (int j = 0; j < 8; j++) {
                int m = mg * 8 + j;
                *(float4*)&sm[OFF_PX + m * 64 + sl0] =
                    make_float4(e[0][j], e[1][j], e[2][j], e[3][j]);
                *(float4*)&sm[OFF_PX + m * 64 + sl1] =
                    make_float4(e[4][j], e[5][j], e[6][j], e[7][j]);
            }
        }
        __syncthreads();

#pragma unroll 4
        for (int st = 0; st < 32; st++) {
            int m = ms * 32 + st, mgp = m >> 3;
            float4 p0 = *(const float4*)&sm[OFF_PX + m * 64 + ((qg2 + mgp) & 15) * 4];
            float4 p1 = *(const float4*)&sm[OFF_PX + m * 64 + ((qg2 + 8 + mgp) & 15) * 4];
            ulonglong2 v0 = *(const ulonglong2*)&sm[OFF_VS + m * 32 + dg * 8];
            ulonglong2 v1 = *(const ulonglong2*)&sm[OFF_VS + m * 32 + dg * 8 + 4];
            u64 vp[4] = {v0.x, v0.y, v1.x, v1.y};
            float pv[8] = {p0.x, p0.y, p0.z, p0.w, p1.x, p1.y, p1.z, p1.w};
#pragma unroll
            for (int i = 0; i < 8; i++) {
                u64 pd = dup2(pv[i]);
#pragma unroll
                for (int j = 0; j < 4; j++) fma2(acc2[i][j], pd, vp[j]);
            }
        }
    }

#pragma unroll
    for (int i = 0; i < 8; i++) {
        float r = runl[i];
        r += __shfl_xor_sync(~0u, r, 8, 16);
        r += __shfl_xor_sync(~0u, r, 4, 16);
        r += __shfl_xor_sync(~0u, r, 2, 16);
        r += __shfl_xor_sync(~0u, r, 1, 16);
        if (mg == 0) sm[OFF_LR + qg * 8 + i] = r;
    }
    __syncthreads();

#pragma unroll
    for (int i = 0; i < 8; i++) {
        int q = qg2 * 8 + i;
        int base = OFF_PX + (ms * 64 + q) * 32 + dg * 8;
        float2 f0 = unpk2(acc2[i][0]), f1 = unpk2(acc2[i][1]);
        float2 f2 = unpk2(acc2[i][2]), f3 = unpk2(acc2[i][3]);
        *(float4*)&sm[base]     = make_float4(f0.x, f0.y, f1.x, f1.y);
        *(float4*)&sm[base + 4] = make_float4(f2.x, f2.y, f3.x, f3.y);
    }
    __syncthreads();

#pragma unroll
    for (int r = 0; r < 16; r++) {
        int idx = t + r * 128;
        int q = idx >> 5, d = idx & 31;
        float c = sm[OFF_PX + q * 32 + d] + sm[OFF_PX + 2048 + q * 32 + d]
                + sm[OFF_PX + 4096 + q * 32 + d] + sm[OFF_PX + 6144 + q * 32 + d];
        sm[OFF_OUT + q * 68 + d] = c / sm[OFF_LR + q];
    }
#pragma unroll
    for (int r = 0; r < 4; r++) {
        int idx = t + r * 128;
        int kk = idx >> 5, d = idx & 31;
        int m = ((int*)sm)[OFF_TXI + kk];
        sm[OFF_TK + kk * 32 + d] = g_fkT[((long)bh * 32 + d) * NQ + m];
        sm[OFF_TV + kk * 32 + d] = g_fvT[((long)bh * 32 + d) * NQ + m];
    }
    __syncthreads();

    {
        const int q = t >> 1, kg = t & 1;
        float qv[32];
#pragma unroll
        for (int d = 0; d < 32; d++) qv[d] = sm[OFF_QT + d * 68 + q];
#pragma unroll
        for (int j = 0; j < 8; j++) {
            int kk = kg * 8 + j;
            float s = 0.0f;
#pragma unroll
            for (int d = 0; d < 32; d++) s += qv[d] * sm[OFF_TK + kk * 32 + d];
            sm[OFF_SC + q * 17 + kk] = __expf(s);
        }
    }
#pragma unroll
    for (int r = 0; r < 16; r++) sm[OFF_GS + t + r * 128] = gate_w[t + r * 128];
    if (t < 32) sm[OFF_GB + t] = gate_b[t];
    __syncthreads();
    if (t < 64) {
        float sum = 0.0f;
#pragma unroll
        for (int kk = 0; kk < NTK; kk++) sum += sm[OFF_SC + t * 17 + kk];
        sm[OFF_SC + t * 17 + 16] = 1.0f / sum;
    }
    __syncthreads();
    {
        const int q = t >> 1, hf = t & 1;
        float inv = sm[OFF_SC + q * 17 + 16];
        float sc[NTK];
#pragma unroll
        for (int kk = 0; kk < NTK; kk++) sc[kk] = sm[OFF_SC + q * 17 + kk];
#pragma unroll
        for (int dd = 0; dd < 16; dd++) {
            int d = hf * 16 + dd;
            float r = 0.0f;
#pragma unroll
            for (int kk = 0; kk < NTK; kk++) r += sc[kk] * sm[OFF_TV + kk * 32 + d];
            sm[OFF_OUT + q * 68 + 32 + d] = r * inv;
        }
    }
    __syncthreads();
    {
        const int q = t >> 1, hf = t & 1;
        float ov[64];
#pragma unroll
        for (int c4 = 0; c4 < 16; c4++)
            *(float4*)&ov[c4 * 4] = *(const float4*)&sm[OFF_OUT + q * 68 + c4 * 4];
        float res[16];
#pragma unroll
        for (int dd = 0; dd < 16; dd++) {
            int d = hf * 16 + dd;
            float g = sm[OFF_GB + d];
#pragma unroll
            for (int c = 0; c < 64; c++) g += ov[c] * sm[OFF_GS + d * 64 + c];
            float gv = 1.0f / (1.0f + __expf(-g));
            res[dd] = gv * sm[OFF_OUT + q * 68 + 32 + d] + (1.0f - gv) * ov[d];
        }
        __syncthreads();
#pragma unroll
        for (int dd = 0; dd < 16; dd++)
            sm[OFF_OUT + q * 68 + hf * 16 + dd] = res[dd];
    }
    __syncthreads();

    float* xo = g_xout + ((long)(b * 256 + h * 32)) * NQ + n0;
#pragma unroll
    for (int r = 0; r < 16; r++) {
        int idx = t + r * 128;
        int d = idx >> 6, q = idx & 63;
        xo[(long)d * NQ + q] = sm[OFF_OUT + q * 68 + d];
    }
}

// ---------------- depthwise 7x7 + bilinear up + add -------------------------
__global__ void __launch_bounds__(256)
dwupadd_kernel(const float* __restrict__ pe_w, const float* __restrict__ pe_b)
{
    int bc = blockIdx.x, t = threadIdx.x;
    __shared__ float tile[38 * 38], wv[49], vpe[1024];
    const float* src = g_vt + (long)bc * NU;
    for (int idx = t; idx < 38 * 38; idx += 256) {
        int ii = idx / 38 - 3, jj = idx % 38 - 3;
        tile[idx] = (ii >= 0 && ii < 32 && jj >= 0 && jj < 32) ? src[ii * 32 + jj] : 0.0f;
    }
    int c = bc & 255;
    if (t < 49) wv[t] = pe_w[c * 49 + t];
    __syncthreads();
    float bias = pe_b[c];
    for (int idx = t; idx < NU; idx += 256) {
        int i = idx >> 5, j = idx & 31;
        float s = bias;
#pragma unroll
        for (int di = 0; di < 7; di++)
#pragma unroll
            for (int dj = 0; dj < 7; dj++)
                s += tile[(i + di) * 38 + (j + dj)] * wv[di * 7 + dj];
        vpe[idx] = s;
    }
    __syncthreads();
    float* xo = g_xout + (long)bc * NQ;
    for (int idx = t; idx < NQ; idx += 256) {
        int I = idx >> 6, J = idx & 63;
        int i0, i1, j0, j1; float wi0, wi1, wj0, wj1;
        if (I & 1) { i0 = I >> 1; wi0 = 0.75f; i1 = min(i0 + 1, 31); wi1 = 0.25f; }
        else       { i1 = I >> 1; wi1 = 0.75f; i0 = max(i1 - 1, 0);  wi0 = 0.25f; }
        if (J & 1) { j0 = J >> 1; wj0 = 0.75f; j1 = min(j0 + 1, 31); wj1 = 0.25f; }
        else       { j1 = J >> 1; wj1 = 0.75f; j0 = max(j1 - 1, 0);  wj0 = 0.25f; }
        xo[idx] += wi0 * (wj0 * vpe[i0 * 32 + j0] + wj1 * vpe[i0 * 32 + j1])
                 + wi1 * (wj0 * vpe[i1 * 32 + j0] + wj1 * vpe[i1 * 32 + j1]);
    }
}

extern "C" void kernel_launch(void* const* d_in, const int* in_sizes, int n_in,
                              void* d_out, int out_size)
{
    const float* x      = (const float*)d_in[0];
    const float* upper  = (const float*)d_in[1];
    const float* q_w    = (const float*)d_in[2];
    const float* q_b    = (const float*)d_in[3];
    const float* kv_w   = (const float*)d_in[4];
    const float* kv_b   = (const float*)d_in[5];
    const float* proj_w = (const float*)d_in[6];
    const float* proj_b = (const float*)d_in[7];
    const float* pe_w   = (const float*)d_in[8];
    const float* pe_b   = (const float*)d_in[9];
    const float* gate_w = (const float*)d_in[10];
    const float* gate_b = (const float*)d_in[11];
    float* out = (float*)d_out;

    cudaFuncSetAttribute(attn_kernel, cudaFuncAttributeMaxDynamicSharedMemorySize,
                         ATTN_SMEM_FLOATS * 4);

    gemm01_kernel<<<448, 256>>>(x, upper, q_w, q_b, kv_w, kv_b);
    qpart_kernel<<<dim3(8, 16), 256>>>();
    topk_kernel<<<16, 256>>>();
    attn_kernel<<<dim3(64, 16), 128, ATTN_SMEM_FLOATS * 4>>>(gate_w, gate_b);
    dwupadd_kernel<<<BATCH * DIM, 256>>>(pe_w, pe_b);
    gemm2_kernel<<<dim3(32, 2, 2), 256>>>(proj_w, proj_b, out);
}